// round 1
// baseline (speedup 1.0000x reference)
#include <cuda_runtime.h>
#include <cstdint>

#define BB   2
#define NN   4096
#define DD   256
#define PC   320     // 3*64 (Wk) + 128 (W_lin)
#define DOUT 64

// ---------------- scratch (static device arrays; no cudaMalloc allowed) ----
__device__ float g_Kb[(size_t)BB * NN * NN];     // 134 MB  b-spline kernel
__device__ float g_Kw[(size_t)BB * NN * NN];     // 134 MB  wavelet kernel
__device__ float g_sq[BB * NN];                  // row squared norms
__device__ float g_Wcat[DD * PC];                // [256,320] = [W0|W1|W2|W_lin]
__device__ float g_P[(size_t)BB * NN * PC];      // x @ Wcat
__device__ float g_t[(size_t)2 * BB * NN * DOUT]; // stage-1: K@h2 + h1
__device__ float g_g[(size_t)2 * BB * NN * DOUT]; // stage-2: K@(h1 + K@h2)

// ---------------- helpers --------------------------------------------------
__device__ __forceinline__ uint32_t f2tf(float f) {
    uint32_t u;
    asm volatile("cvt.rna.tf32.f32 %0, %1;" : "=r"(u) : "f"(f));
    return u;
}

__device__ __forceinline__ void mma_tf32(float c[4], const uint32_t a[4], const uint32_t b[2]) {
    asm volatile(
        "mma.sync.aligned.m16n8k8.row.col.f32.tf32.tf32.f32 "
        "{%0,%1,%2,%3}, {%4,%5,%6,%7}, {%8,%9}, {%0,%1,%2,%3};\n"
        : "+f"(c[0]), "+f"(c[1]), "+f"(c[2]), "+f"(c[3])
        : "r"(a[0]), "r"(a[1]), "r"(a[2]), "r"(a[3]),
          "r"(b[0]), "r"(b[1]));
}

// Cox-de Boor N_{0,3}(t), uniform knots {0,.25,.5,.75,1} — exact reference recursion.
__device__ __forceinline__ float bspline3(float t) {
    float b00 = (t >= 0.00f && t < 0.25f) ? 1.f : 0.f;
    float b01 = (t >= 0.25f && t < 0.50f) ? 1.f : 0.f;
    float b02 = (t >= 0.50f && t < 0.75f) ? 1.f : 0.f;
    float b03 = (t >= 0.75f && t < 1.00f) ? 1.f : 0.f;
    float b10 = (t - 0.00f) * 4.f * b00 + (0.50f - t) * 4.f * b01;
    float b11 = (t - 0.25f) * 4.f * b01 + (0.75f - t) * 4.f * b02;
    float b12 = (t - 0.50f) * 4.f * b02 + (1.00f - t) * 4.f * b03;
    float b20 = (t - 0.00f) * 2.f * b10 + (0.75f - t) * 2.f * b11;
    float b21 = (t - 0.25f) * 2.f * b11 + (1.00f - t) * 2.f * b12;
    const float i34 = 1.f / 0.75f;
    return (t - 0.00f) * i34 * b20 + (1.00f - t) * i34 * b21;
}

// ---------------- kernel 1: squared row norms ------------------------------
__global__ void k_sqnorm(const float* __restrict__ x) {
    int row  = blockIdx.x * 8 + (threadIdx.x >> 5);
    int lane = threadIdx.x & 31;
    const float* xr = x + (size_t)row * DD;
    float s = 0.f;
    #pragma unroll
    for (int i = lane; i < DD; i += 32) { float v = xr[i]; s += v * v; }
    #pragma unroll
    for (int o = 16; o; o >>= 1) s += __shfl_xor_sync(0xffffffffu, s, o);
    if (lane == 0) g_sq[row] = s;
}

// ---------------- kernel 2: pack Wcat = [W0|W1|W2|W_lin] -------------------
__global__ void k_wcat(const float* __restrict__ Wk, const float* __restrict__ Wl) {
    int i = blockIdx.x * 256 + threadIdx.x;
    if (i >= DD * PC) return;
    int d = i / PC, cidx = i % PC;
    float v;
    if (cidx < 192) v = Wk[(size_t)(cidx / 64) * DD * 64 + (size_t)d * 64 + (cidx & 63)];
    else            v = Wl[(size_t)d * 128 + (cidx - 192)];
    g_Wcat[i] = v;
}

// ---------------- kernel 3: Gram + spline (symmetric, fused) ---------------
// 128x128 tile per block, 8 warps (2m x 4n), warp tile 64x32, tf32 mma.
__global__ __launch_bounds__(256) void k_gram(const float* __restrict__ x) {
    int tj = blockIdx.x, ti = blockIdx.y, b = blockIdx.z;
    if (ti > tj) return;
    __shared__ uint32_t As[32][132];
    __shared__ uint32_t Bs[32][132];
    const float* xb = x + (size_t)b * NN * DD;
    int tid = threadIdx.x, lane = tid & 31, wid = tid >> 5;
    int wm = wid & 1, wn = wid >> 1;

    float c[4][4][4];
    #pragma unroll
    for (int i = 0; i < 4; i++)
        #pragma unroll
        for (int j = 0; j < 4; j++)
            #pragma unroll
            for (int r = 0; r < 4; r++) c[i][j][r] = 0.f;

    for (int k0 = 0; k0 < DD; k0 += 32) {
        #pragma unroll
        for (int it = 0; it < 4; ++it) {
            int idx = it * 256 + tid;
            int m = idx >> 3, kq = (idx & 7) << 2;
            float4 va = *(const float4*)(xb + (size_t)(ti * 128 + m) * DD + k0 + kq);
            As[kq + 0][m] = f2tf(va.x); As[kq + 1][m] = f2tf(va.y);
            As[kq + 2][m] = f2tf(va.z); As[kq + 3][m] = f2tf(va.w);
            float4 vb = *(const float4*)(xb + (size_t)(tj * 128 + m) * DD + k0 + kq);
            Bs[kq + 0][m] = f2tf(vb.x); Bs[kq + 1][m] = f2tf(vb.y);
            Bs[kq + 2][m] = f2tf(vb.z); Bs[kq + 3][m] = f2tf(vb.w);
        }
        __syncthreads();
        #pragma unroll
        for (int ks = 0; ks < 4; ++ks) {
            int kk = ks * 8 + (lane & 3);
            uint32_t a[4][4], bf[4][2];
            #pragma unroll
            for (int mi = 0; mi < 4; mi++) {
                int mr = wm * 64 + mi * 16 + (lane >> 2);
                a[mi][0] = As[kk][mr];     a[mi][1] = As[kk][mr + 8];
                a[mi][2] = As[kk + 4][mr]; a[mi][3] = As[kk + 4][mr + 8];
            }
            #pragma unroll
            for (int ni = 0; ni < 4; ni++) {
                int nc = wn * 32 + ni * 8 + (lane >> 2);
                bf[ni][0] = Bs[kk][nc]; bf[ni][1] = Bs[kk + 4][nc];
            }
            #pragma unroll
            for (int mi = 0; mi < 4; mi++)
                #pragma unroll
                for (int ni = 0; ni < 4; ni++)
                    mma_tf32(c[mi][ni], a[mi], bf[ni]);
        }
        __syncthreads();
    }

    float* Kb = g_Kb + (size_t)b * NN * NN;
    float* Kw = g_Kw + (size_t)b * NN * NN;
    const float* sq = g_sq + b * NN;
    int i0 = ti * 128 + wm * 64, j0 = tj * 128 + wn * 32;
    bool mir = (ti != tj);
    #pragma unroll
    for (int mi = 0; mi < 4; mi++) {
        #pragma unroll
        for (int ni = 0; ni < 4; ni++) {
            #pragma unroll
            for (int r = 0; r < 4; r++) {
                int i = i0 + mi * 16 + (lane >> 2) + ((r >> 1) << 3);
                int j = j0 + ni * 8 + ((lane & 3) << 1) + (r & 1);
                float d2 = sq[i] + sq[j] - 2.f * c[mi][ni][r];
                d2 = fmaxf(d2, 0.f);
                float t = __expf(d2 * (-1.f / 512.f));
                float bk = bspline3(t);
                float wk = bspline3(2.f * t) - bspline3(2.f * t - 1.f);
                Kb[(size_t)i * NN + j] = bk;
                Kw[(size_t)i * NN + j] = wk;
                if (mir) {
                    Kb[(size_t)j * NN + i] = bk;
                    Kw[(size_t)j * NN + i] = wk;
                }
            }
        }
    }
}

// ---------------- kernel 4: projection P = x @ Wcat ------------------------
// block tile 128x64, 8 warps (2m x 4n), warp tile 64x16.
__global__ __launch_bounds__(256) void k_proj(const float* __restrict__ x) {
    int bxc = blockIdx.x;          // col tile (0..4)
    int byr = blockIdx.y;          // row tile (0..63) over B*N
    __shared__ uint32_t As[32][132];
    __shared__ uint32_t Bs[32][68];
    int tid = threadIdx.x, lane = tid & 31, wid = tid >> 5;
    int wm = wid & 1, wn = wid >> 1;
    int c0 = bxc * 64;

    float c[4][2][4];
    #pragma unroll
    for (int i = 0; i < 4; i++)
        #pragma unroll
        for (int j = 0; j < 2; j++)
            #pragma unroll
            for (int r = 0; r < 4; r++) c[i][j][r] = 0.f;

    for (int k0 = 0; k0 < DD; k0 += 32) {
        #pragma unroll
        for (int it = 0; it < 4; ++it) {
            int idx = it * 256 + tid;
            int m = idx >> 3, kq = (idx & 7) << 2;
            float4 v = *(const float4*)(x + (size_t)(byr * 128 + m) * DD + k0 + kq);
            As[kq + 0][m] = f2tf(v.x); As[kq + 1][m] = f2tf(v.y);
            As[kq + 2][m] = f2tf(v.z); As[kq + 3][m] = f2tf(v.w);
        }
        #pragma unroll
        for (int it = 0; it < 2; ++it) {
            int idx = it * 256 + tid;
            int kk = idx >> 4, cq = (idx & 15) << 2;
            float4 v = *(const float4*)(g_Wcat + (size_t)(k0 + kk) * PC + c0 + cq);
            Bs[kk][cq + 0] = f2tf(v.x); Bs[kk][cq + 1] = f2tf(v.y);
            Bs[kk][cq + 2] = f2tf(v.z); Bs[kk][cq + 3] = f2tf(v.w);
        }
        __syncthreads();
        #pragma unroll
        for (int ks = 0; ks < 4; ++ks) {
            int kk = ks * 8 + (lane & 3);
            uint32_t a[4][4], bf[2][2];
            #pragma unroll
            for (int mi = 0; mi < 4; mi++) {
                int mr = wm * 64 + mi * 16 + (lane >> 2);
                a[mi][0] = As[kk][mr];     a[mi][1] = As[kk][mr + 8];
                a[mi][2] = As[kk + 4][mr]; a[mi][3] = As[kk + 4][mr + 8];
            }
            #pragma unroll
            for (int ni = 0; ni < 2; ni++) {
                int nc = wn * 16 + ni * 8 + (lane >> 2);
                bf[ni][0] = Bs[kk][nc]; bf[ni][1] = Bs[kk + 4][nc];
            }
            #pragma unroll
            for (int mi = 0; mi < 4; mi++)
                #pragma unroll
                for (int ni = 0; ni < 2; ni++)
                    mma_tf32(c[mi][ni], a[mi], bf[ni]);
        }
        __syncthreads();
    }
    #pragma unroll
    for (int mi = 0; mi < 4; mi++)
        #pragma unroll
        for (int ni = 0; ni < 2; ni++)
            #pragma unroll
            for (int r = 0; r < 4; r++) {
                int row = byr * 128 + wm * 64 + mi * 16 + (lane >> 2) + ((r >> 1) << 3);
                int col = c0 + wn * 16 + ni * 8 + ((lane & 3) << 1) + (r & 1);
                g_P[(size_t)row * PC + col] = c[mi][ni][r];
            }
}

// ---------------- kernel 5: SpMM C = K @ H (+Add) --------------------------
// block tile 128x64 over rows x 64 output cols, contraction 4096 in 32-chunks.
__global__ __launch_bounds__(256) void k_spmm(int stage) {
    int rt = blockIdx.x, b = blockIdx.y, type = blockIdx.z;
    const float* Km = (type ? g_Kw : g_Kb) + (size_t)b * NN * NN;
    const float* H; int ldh; const float* Add; float* Out;
    if (stage == 1) {
        H   = g_P + (size_t)b * NN * PC + 128;  ldh = PC;   // h2 = x@W2
        Add = g_P + (size_t)b * NN * PC + 64;               // h1 = x@W1
        Out = g_t + ((size_t)type * BB + b) * NN * DOUT;
    } else {
        H   = g_t + ((size_t)type * BB + b) * NN * DOUT; ldh = DOUT;
        Add = nullptr;
        Out = g_g + ((size_t)type * BB + b) * NN * DOUT;
    }
    __shared__ uint32_t As[32][132];
    __shared__ uint32_t Bs[32][68];
    int tid = threadIdx.x, lane = tid & 31, wid = tid >> 5;
    int wm = wid & 1, wn = wid >> 1;

    float c[4][2][4];
    #pragma unroll
    for (int i = 0; i < 4; i++)
        #pragma unroll
        for (int j = 0; j < 2; j++)
            #pragma unroll
            for (int r = 0; r < 4; r++) c[i][j][r] = 0.f;

    #pragma unroll 1
    for (int m0 = 0; m0 < NN; m0 += 32) {
        #pragma unroll
        for (int it = 0; it < 4; ++it) {
            int idx = it * 256 + tid;
            int m = idx >> 3, kq = (idx & 7) << 2;
            float4 v = *(const float4*)(Km + (size_t)(rt * 128 + m) * NN + m0 + kq);
            As[kq + 0][m] = f2tf(v.x); As[kq + 1][m] = f2tf(v.y);
            As[kq + 2][m] = f2tf(v.z); As[kq + 3][m] = f2tf(v.w);
        }
        #pragma unroll
        for (int it = 0; it < 2; ++it) {
            int idx = it * 256 + tid;
            int kk = idx >> 4, cq = (idx & 15) << 2;
            float4 v = *(const float4*)(H + (size_t)(m0 + kk) * ldh + cq);
            Bs[kk][cq + 0] = f2tf(v.x); Bs[kk][cq + 1] = f2tf(v.y);
            Bs[kk][cq + 2] = f2tf(v.z); Bs[kk][cq + 3] = f2tf(v.w);
        }
        __syncthreads();
        #pragma unroll
        for (int ks = 0; ks < 4; ++ks) {
            int kk = ks * 8 + (lane & 3);
            uint32_t a[4][4], bf[2][2];
            #pragma unroll
            for (int mi = 0; mi < 4; mi++) {
                int mr = wm * 64 + mi * 16 + (lane >> 2);
                a[mi][0] = As[kk][mr];     a[mi][1] = As[kk][mr + 8];
                a[mi][2] = As[kk + 4][mr]; a[mi][3] = As[kk + 4][mr + 8];
            }
            #pragma unroll
            for (int ni = 0; ni < 2; ni++) {
                int nc = wn * 16 + ni * 8 + (lane >> 2);
                bf[ni][0] = Bs[kk][nc]; bf[ni][1] = Bs[kk + 4][nc];
            }
            #pragma unroll
            for (int mi = 0; mi < 4; mi++)
                #pragma unroll
                for (int ni = 0; ni < 2; ni++)
                    mma_tf32(c[mi][ni], a[mi], bf[ni]);
        }
        __syncthreads();
    }
    #pragma unroll
    for (int mi = 0; mi < 4; mi++)
        #pragma unroll
        for (int ni = 0; ni < 2; ni++)
            #pragma unroll
            for (int r = 0; r < 4; r++) {
                int row = rt * 128 + wm * 64 + mi * 16 + (lane >> 2) + ((r >> 1) << 3);
                int col = wn * 16 + ni * 8 + ((lane & 3) << 1) + (r & 1);
                float v = c[mi][ni][r];
                if (Add) v += Add[(size_t)row * PC + col];
                Out[(size_t)row * DOUT + col] = v;
            }
}

// ---------------- kernel 6: final epilogue ---------------------------------
__global__ void k_final(const float* __restrict__ b_lin, float* __restrict__ out) {
    int idx = blockIdx.x * 256 + threadIdx.x;          // over B*N*128
    int cidx = idx & 127;
    int n = (idx >> 7) & (NN - 1);
    int b = idx >> 19;
    int half = cidx >> 6, cc = cidx & 63;
    const float* P = g_P + ((size_t)b * NN + n) * PC;
    float g = g_g[(((size_t)half * BB + b) * NN + n) * DOUT + cc];
    float v = P[cc] + g + P[192 + cidx] + b_lin[cidx];
    out[idx] = fmaxf(v, 0.f);
}

// ---------------- launch ---------------------------------------------------
extern "C" void kernel_launch(void* const* d_in, const int* in_sizes, int n_in,
                              void* d_out, int out_size) {
    const float* x  = (const float*)d_in[0];
    const float* Wk = (const float*)d_in[1];
    const float* Wl = (const float*)d_in[2];
    const float* bl = (const float*)d_in[3];
    float* out = (float*)d_out;

    k_sqnorm<<<BB * NN / 8, 256>>>(x);
    k_wcat<<<(DD * PC + 255) / 256, 256>>>(Wk, Wl);
    k_gram<<<dim3(NN / 128, NN / 128, BB), 256>>>(x);
    k_proj<<<dim3(PC / 64, (BB * NN) / 128), 256>>>(x);
    k_spmm<<<dim3(NN / 128, BB, 2), 256>>>(1);
    k_spmm<<<dim3(NN / 128, BB, 2), 256>>>(2);
    k_final<<<(BB * NN * 128) / 256, 256>>>(bl, out);
}

// round 2
// speedup vs baseline: 1.6272x; 1.6272x over previous
#include <cuda_runtime.h>
#include <cstdint>

#define BB   2
#define NN   4096
#define DD   256
#define PC   320     // 3*64 (Wk) + 128 (W_lin)
#define DOUT 64

// ---------------- scratch ---------------------------------------------------
__device__ float g_Kb[(size_t)BB * NN * NN];      // tf32-rounded b-spline kernel
__device__ float g_Kw[(size_t)BB * NN * NN];      // tf32-rounded wavelet kernel
__device__ float g_sq[BB * NN];
__device__ float g_Wcat[DD * PC];                 // tf32-rounded [W0|W1|W2|W_lin]
__device__ float g_Xt[(size_t)BB * NN * DD];      // tf32-rounded x
__device__ float g_P[(size_t)BB * NN * PC];       // full fp32 x@Wcat
__device__ float g_H2r[(size_t)BB * NN * DOUT];   // tf32-rounded h2 (cols 128..191 of P)
__device__ float g_t[(size_t)2 * BB * NN * DOUT]; // tf32-rounded stage-1 out
__device__ float g_g[(size_t)2 * BB * NN * DOUT]; // full fp32 stage-2 out

// ---------------- helpers ---------------------------------------------------
__device__ __forceinline__ uint32_t f2tf(float f) {
    uint32_t u;
    asm volatile("cvt.rna.tf32.f32 %0, %1;" : "=r"(u) : "f"(f));
    return u;
}

__device__ __forceinline__ void mma_tf32(float c[4], const uint32_t a[4], const uint32_t b[2]) {
    asm volatile(
        "mma.sync.aligned.m16n8k8.row.col.f32.tf32.tf32.f32 "
        "{%0,%1,%2,%3}, {%4,%5,%6,%7}, {%8,%9}, {%0,%1,%2,%3};\n"
        : "+f"(c[0]), "+f"(c[1]), "+f"(c[2]), "+f"(c[3])
        : "r"(a[0]), "r"(a[1]), "r"(a[2]), "r"(a[3]),
          "r"(b[0]), "r"(b[1]));
}

__device__ __forceinline__ void cpa16(uint32_t dst, const float* src) {
    asm volatile("cp.async.cg.shared.global [%0], [%1], 16;\n" :: "r"(dst), "l"(src));
}
#define CP_COMMIT() asm volatile("cp.async.commit_group;\n" ::: "memory")
#define CP_WAIT1()  asm volatile("cp.async.wait_group 1;\n" ::: "memory")

__device__ __forceinline__ float bspline3(float t) {
    float b00 = (t >= 0.00f && t < 0.25f) ? 1.f : 0.f;
    float b01 = (t >= 0.25f && t < 0.50f) ? 1.f : 0.f;
    float b02 = (t >= 0.50f && t < 0.75f) ? 1.f : 0.f;
    float b03 = (t >= 0.75f && t < 1.00f) ? 1.f : 0.f;
    float b10 = (t - 0.00f) * 4.f * b00 + (0.50f - t) * 4.f * b01;
    float b11 = (t - 0.25f) * 4.f * b01 + (0.75f - t) * 4.f * b02;
    float b12 = (t - 0.50f) * 4.f * b02 + (1.00f - t) * 4.f * b03;
    float b20 = (t - 0.00f) * 2.f * b10 + (0.75f - t) * 2.f * b11;
    float b21 = (t - 0.25f) * 2.f * b11 + (1.00f - t) * 2.f * b12;
    const float i34 = 1.f / 0.75f;
    return (t - 0.00f) * i34 * b20 + (1.00f - t) * i34 * b21;
}

// ---------------- tiny prep kernels -----------------------------------------
__global__ void k_xcvt(const float* __restrict__ x) {
    int i = blockIdx.x * 256 + threadIdx.x;              // over 2M/4 float4
    float4 v = ((const float4*)x)[i];
    uint4 o;
    o.x = f2tf(v.x); o.y = f2tf(v.y); o.z = f2tf(v.z); o.w = f2tf(v.w);
    ((uint4*)g_Xt)[i] = o;
}

__global__ void k_sqnorm(const float* __restrict__ x) {
    int row  = blockIdx.x * 8 + (threadIdx.x >> 5);
    int lane = threadIdx.x & 31;
    const float* xr = x + (size_t)row * DD;
    float s = 0.f;
    #pragma unroll
    for (int i = lane; i < DD; i += 32) { float v = xr[i]; s += v * v; }
    #pragma unroll
    for (int o = 16; o; o >>= 1) s += __shfl_xor_sync(0xffffffffu, s, o);
    if (lane == 0) g_sq[row] = s;
}

__global__ void k_wcat(const float* __restrict__ Wk, const float* __restrict__ Wl) {
    int i = blockIdx.x * 256 + threadIdx.x;
    if (i >= DD * PC) return;
    int d = i / PC, cidx = i % PC;
    float v;
    if (cidx < 192) v = Wk[(size_t)(cidx / 64) * DD * 64 + (size_t)d * 64 + (cidx & 63)];
    else            v = Wl[(size_t)d * 128 + (cidx - 192)];
    g_Wcat[i] = __uint_as_float(f2tf(v));
}

// ---------------- kernel: Gram + spline (symmetric, pipelined) --------------
// Triangular grid (528 tiles/batch), 128x128 tile, 8 warps 2m x 4n, KC=16.
// smem: 2 stages x (A 128x20 + B 128x20) = 40960 B.
__global__ __launch_bounds__(256) void k_gram() {
    __shared__ float sm[2 * 2 * 2560];
    int idx = blockIdx.x, b = blockIdx.y;
    int tj = (int)((sqrtf(8.f * idx + 1.f) - 1.f) * 0.5f);
    while ((tj + 1) * (tj + 2) / 2 <= idx) ++tj;
    while (tj * (tj + 1) / 2 > idx) --tj;
    int ti = idx - tj * (tj + 1) / 2;

    int tid = threadIdx.x, lane = tid & 31, wid = tid >> 5;
    int wm = wid & 1, wn = wid >> 1;
    const float* Xa = g_Xt + ((size_t)b * NN + (size_t)ti * 128) * DD;
    const float* Xb = g_Xt + ((size_t)b * NN + (size_t)tj * 128) * DD;
    uint32_t sb = (uint32_t)__cvta_generic_to_shared(sm);

    float c[4][4][4];
    #pragma unroll
    for (int i = 0; i < 4; i++)
        #pragma unroll
        for (int j = 0; j < 4; j++)
            #pragma unroll
            for (int r = 0; r < 4; r++) c[i][j][r] = 0.f;

    // prologue: chunk 0 -> stage 0
    {
        uint32_t sA = sb, sB = sb + 2560 * 4;
        #pragma unroll
        for (int it = 0; it < 2; ++it) {
            int id = it * 256 + tid;
            int row = id >> 2, part = (id & 3) << 2;
            cpa16(sA + (row * 20 + part) * 4, Xa + (size_t)row * DD + part);
            cpa16(sB + (row * 20 + part) * 4, Xb + (size_t)row * DD + part);
        }
    }
    CP_COMMIT();

    for (int cc = 0; cc < 16; ++cc) {
        if (cc + 1 < 16) {
            int s = (cc + 1) & 1, k0 = (cc + 1) * 16;
            uint32_t sA = sb + (s * 5120) * 4, sB = sA + 2560 * 4;
            #pragma unroll
            for (int it = 0; it < 2; ++it) {
                int id = it * 256 + tid;
                int row = id >> 2, part = (id & 3) << 2;
                cpa16(sA + (row * 20 + part) * 4, Xa + (size_t)row * DD + k0 + part);
                cpa16(sB + (row * 20 + part) * 4, Xb + (size_t)row * DD + k0 + part);
            }
        }
        CP_COMMIT();
        CP_WAIT1();
        __syncthreads();
        const float* A  = sm + (cc & 1) * 5120;
        const float* Bp = A + 2560;
        #pragma unroll
        for (int ks = 0; ks < 2; ++ks) {
            int kk = ks * 8 + (lane & 3);
            uint32_t a[4][4], bf[4][2];
            #pragma unroll
            for (int mi = 0; mi < 4; mi++) {
                int mr = wm * 64 + mi * 16 + (lane >> 2);
                a[mi][0] = __float_as_uint(A[mr * 20 + kk]);
                a[mi][1] = __float_as_uint(A[(mr + 8) * 20 + kk]);
                a[mi][2] = __float_as_uint(A[mr * 20 + kk + 4]);
                a[mi][3] = __float_as_uint(A[(mr + 8) * 20 + kk + 4]);
            }
            #pragma unroll
            for (int ni = 0; ni < 4; ni++) {
                int nc = wn * 32 + ni * 8 + (lane >> 2);
                bf[ni][0] = __float_as_uint(Bp[nc * 20 + kk]);
                bf[ni][1] = __float_as_uint(Bp[nc * 20 + kk + 4]);
            }
            #pragma unroll
            for (int mi = 0; mi < 4; mi++)
                #pragma unroll
                for (int ni = 0; ni < 4; ni++)
                    mma_tf32(c[mi][ni], a[mi], bf[ni]);
        }
        __syncthreads();
    }

    float* Kb = g_Kb + (size_t)b * NN * NN;
    float* Kw = g_Kw + (size_t)b * NN * NN;
    const float* sq = g_sq + b * NN;
    int i0 = ti * 128 + wm * 64, j0 = tj * 128 + wn * 32;
    bool mir = (ti != tj);
    #pragma unroll
    for (int mi = 0; mi < 4; mi++)
        #pragma unroll
        for (int ni = 0; ni < 4; ni++)
            #pragma unroll
            for (int r = 0; r < 4; r++) {
                int i = i0 + mi * 16 + (lane >> 2) + ((r >> 1) << 3);
                int j = j0 + ni * 8 + ((lane & 3) << 1) + (r & 1);
                float d2 = sq[i] + sq[j] - 2.f * c[mi][ni][r];
                d2 = fmaxf(d2, 0.f);
                float t = __expf(d2 * (-1.f / 512.f));
                float bk = __uint_as_float(f2tf(bspline3(t)));
                float wk = __uint_as_float(f2tf(bspline3(2.f * t) - bspline3(2.f * t - 1.f)));
                Kb[(size_t)i * NN + j] = bk;
                Kw[(size_t)i * NN + j] = wk;
                if (mir) {
                    Kb[(size_t)j * NN + i] = bk;
                    Kw[(size_t)j * NN + i] = wk;
                }
            }
}

// ---------------- kernel: projection P = x @ Wcat (pipelined) ---------------
// 128x64 tile, 8 warps 2m x 4n (warp 64x16), KC=16.
// smem: 2 stages x (A 128x20 + B 16x68) = 29184 B.
__global__ __launch_bounds__(256) void k_proj() {
    __shared__ float sm[2 * 3648];
    int c0 = blockIdx.x * 64, byr = blockIdx.y;
    int tid = threadIdx.x, lane = tid & 31, wid = tid >> 5;
    int wm = wid & 1, wn = wid >> 1;
    const float* Xa = g_Xt + (size_t)byr * 128 * DD;
    uint32_t sb = (uint32_t)__cvta_generic_to_shared(sm);

    float c[4][2][4];
    #pragma unroll
    for (int i = 0; i < 4; i++)
        #pragma unroll
        for (int j = 0; j < 2; j++)
            #pragma unroll
            for (int r = 0; r < 4; r++) c[i][j][r] = 0.f;

    {
        uint32_t sA = sb, sB = sb + 2560 * 4;
        #pragma unroll
        for (int it = 0; it < 2; ++it) {
            int id = it * 256 + tid;
            int row = id >> 2, part = (id & 3) << 2;
            cpa16(sA + (row * 20 + part) * 4, Xa + (size_t)row * DD + part);
        }
        int kk = tid >> 4, cq = (tid & 15) << 2;
        cpa16(sB + (kk * 68 + cq) * 4, g_Wcat + (size_t)kk * PC + c0 + cq);
    }
    CP_COMMIT();

    for (int cc = 0; cc < 16; ++cc) {
        if (cc + 1 < 16) {
            int s = (cc + 1) & 1, k0 = (cc + 1) * 16;
            uint32_t sA = sb + (s * 3648) * 4, sB = sA + 2560 * 4;
            #pragma unroll
            for (int it = 0; it < 2; ++it) {
                int id = it * 256 + tid;
                int row = id >> 2, part = (id & 3) << 2;
                cpa16(sA + (row * 20 + part) * 4, Xa + (size_t)row * DD + k0 + part);
            }
            int kk = tid >> 4, cq = (tid & 15) << 2;
            cpa16(sB + (kk * 68 + cq) * 4, g_Wcat + (size_t)(k0 + kk) * PC + c0 + cq);
        }
        CP_COMMIT();
        CP_WAIT1();
        __syncthreads();
        const float* A  = sm + (cc & 1) * 3648;
        const float* Bp = A + 2560;
        #pragma unroll
        for (int ks = 0; ks < 2; ++ks) {
            int kk = ks * 8 + (lane & 3);
            uint32_t a[4][4], bf[2][2];
            #pragma unroll
            for (int mi = 0; mi < 4; mi++) {
                int mr = wm * 64 + mi * 16 + (lane >> 2);
                a[mi][0] = __float_as_uint(A[mr * 20 + kk]);
                a[mi][1] = __float_as_uint(A[(mr + 8) * 20 + kk]);
                a[mi][2] = __float_as_uint(A[mr * 20 + kk + 4]);
                a[mi][3] = __float_as_uint(A[(mr + 8) * 20 + kk + 4]);
            }
            #pragma unroll
            for (int ni = 0; ni < 2; ni++) {
                int nc = wn * 16 + ni * 8 + (lane >> 2);
                bf[ni][0] = __float_as_uint(Bp[kk * 68 + nc]);
                bf[ni][1] = __float_as_uint(Bp[(kk + 4) * 68 + nc]);
            }
            #pragma unroll
            for (int mi = 0; mi < 4; mi++)
                #pragma unroll
                for (int ni = 0; ni < 2; ni++)
                    mma_tf32(c[mi][ni], a[mi], bf[ni]);
        }
        __syncthreads();
    }

    #pragma unroll
    for (int mi = 0; mi < 4; mi++)
        #pragma unroll
        for (int ni = 0; ni < 2; ni++)
            #pragma unroll
            for (int r = 0; r < 4; r++) {
                int row = byr * 128 + wm * 64 + mi * 16 + (lane >> 2) + ((r >> 1) << 3);
                int col = c0 + wn * 16 + ni * 8 + ((lane & 3) << 1) + (r & 1);
                float v = c[mi][ni][r];
                g_P[(size_t)row * PC + col] = v;
                if (col >= 128 && col < 192)
                    g_H2r[(size_t)row * DOUT + (col - 128)] = __uint_as_float(f2tf(v));
            }
}

// ---------------- kernel: SpMM C = K @ H (+Add) (pipelined) -----------------
// 64x64 tile, 8 warps 4m x 2n (warp 16x32), KC=32, contraction 4096.
// smem: 2 stages x (A 64x36 + B 32x68) = 35840 B. All inputs pre-tf32.
__global__ __launch_bounds__(256) void k_spmm(int stage) {
    __shared__ float sm[2 * 4480];
    int rt = blockIdx.x, b = blockIdx.y, type = blockIdx.z;
    const float* Km = (type ? g_Kw : g_Kb) + (size_t)b * NN * NN;
    const float* H;
    const float* Add;
    float* Out;
    if (stage == 1) {
        H   = g_H2r + (size_t)b * NN * DOUT;
        Add = g_P + (size_t)b * NN * PC + 64;
        Out = g_t + ((size_t)type * BB + b) * NN * DOUT;
    } else {
        H   = g_t + ((size_t)type * BB + b) * NN * DOUT;
        Add = nullptr;
        Out = g_g + ((size_t)type * BB + b) * NN * DOUT;
    }
    int tid = threadIdx.x, lane = tid & 31, wid = tid >> 5;
    int wm = wid & 3, wn = wid >> 2;
    uint32_t sb = (uint32_t)__cvta_generic_to_shared(sm);

    float c[4][4];
    #pragma unroll
    for (int i = 0; i < 4; i++)
        #pragma unroll
        for (int r = 0; r < 4; r++) c[i][r] = 0.f;

    {
        uint32_t sA = sb, sB = sb + 2304 * 4;
        #pragma unroll
        for (int it = 0; it < 2; ++it) {
            int id = it * 256 + tid;
            int row = id >> 3, part = (id & 7) << 2;
            cpa16(sA + (row * 36 + part) * 4, Km + (size_t)(rt * 64 + row) * NN + part);
            int kk = id >> 4, cq = (id & 15) << 2;
            cpa16(sB + (kk * 68 + cq) * 4, H + (size_t)kk * DOUT + cq);
        }
    }
    CP_COMMIT();

    #pragma unroll 1
    for (int cc = 0; cc < 128; ++cc) {
        if (cc + 1 < 128) {
            int s = (cc + 1) & 1, m0 = (cc + 1) * 32;
            uint32_t sA = sb + (s * 4480) * 4, sB = sA + 2304 * 4;
            #pragma unroll
            for (int it = 0; it < 2; ++it) {
                int id = it * 256 + tid;
                int row = id >> 3, part = (id & 7) << 2;
                cpa16(sA + (row * 36 + part) * 4, Km + (size_t)(rt * 64 + row) * NN + m0 + part);
                int kk = id >> 4, cq = (id & 15) << 2;
                cpa16(sB + (kk * 68 + cq) * 4, H + (size_t)(m0 + kk) * DOUT + cq);
            }
        }
        CP_COMMIT();
        CP_WAIT1();
        __syncthreads();
        const float* A  = sm + (cc & 1) * 4480;
        const float* Bp = A + 2304;
        #pragma unroll
        for (int ks = 0; ks < 4; ++ks) {
            int kk = ks * 8 + (lane & 3);
            uint32_t a[4];
            int mr = wm * 16 + (lane >> 2);
            a[0] = __float_as_uint(A[mr * 36 + kk]);
            a[1] = __float_as_uint(A[(mr + 8) * 36 + kk]);
            a[2] = __float_as_uint(A[mr * 36 + kk + 4]);
            a[3] = __float_as_uint(A[(mr + 8) * 36 + kk + 4]);
            #pragma unroll
            for (int ni = 0; ni < 4; ni++) {
                int nc = wn * 32 + ni * 8 + (lane >> 2);
                uint32_t bf[2];
                bf[0] = __float_as_uint(Bp[kk * 68 + nc]);
                bf[1] = __float_as_uint(Bp[(kk + 4) * 68 + nc]);
                mma_tf32(c[ni], a, bf);
            }
        }
        __syncthreads();
    }

    #pragma unroll
    for (int ni = 0; ni < 4; ni++)
        #pragma unroll
        for (int r = 0; r < 4; r++) {
            int row = rt * 64 + wm * 16 + (lane >> 2) + ((r >> 1) << 3);
            int col = wn * 32 + ni * 8 + ((lane & 3) << 1) + (r & 1);
            float v = c[ni][r];
            if (stage == 1) {
                v += Add[(size_t)row * PC + col];
                Out[(size_t)row * DOUT + col] = __uint_as_float(f2tf(v));
            } else {
                Out[(size_t)row * DOUT + col] = v;
            }
        }
}

// ---------------- kernel: final epilogue ------------------------------------
__global__ void k_final(const float* __restrict__ b_lin, float* __restrict__ out) {
    int idx = blockIdx.x * 256 + threadIdx.x;          // over B*N*128
    int cidx = idx & 127;
    int n = (idx >> 7) & (NN - 1);
    int b = idx >> 19;
    int half = cidx >> 6, cc = cidx & 63;
    const float* P = g_P + ((size_t)b * NN + n) * PC;
    float g = g_g[(((size_t)half * BB + b) * NN + n) * DOUT + cc];
    float v = P[cc] + g + P[192 + cidx] + b_lin[cidx];
    out[idx] = fmaxf(v, 0.f);
}

// ---------------- launch ----------------------------------------------------
extern "C" void kernel_launch(void* const* d_in, const int* in_sizes, int n_in,
                              void* d_out, int out_size) {
    const float* x  = (const float*)d_in[0];
    const float* Wk = (const float*)d_in[1];
    const float* Wl = (const float*)d_in[2];
    const float* bl = (const float*)d_in[3];
    float* out = (float*)d_out;

    k_xcvt<<<(BB * NN * DD / 4) / 256, 256>>>(x);
    k_sqnorm<<<BB * NN / 8, 256>>>(x);
    k_wcat<<<(DD * PC + 255) / 256, 256>>>(Wk, Wl);
    k_gram<<<dim3(528, BB), 256>>>();
    k_proj<<<dim3(PC / 64, (BB * NN) / 128), 256>>>();
    k_spmm<<<dim3(NN / 64, BB, 2), 256>>>(1);
    k_spmm<<<dim3(NN / 64, BB, 2), 256>>>(2);
    k_final<<<(BB * NN * 128) / 256, 256>>>(bl, out);
}